// round 5
// baseline (speedup 1.0000x reference)
#include <cuda_runtime.h>
#include <math.h>

// R4: identical to R0-R3 baseline. Four consecutive broker
// GPUAcquisitionTimeouts — the kernel has never run. Resubmitting unchanged:
// the baseline is the highest-expected-information submission per successful
// hold (guaranteed-correct fp32 -> baseline time + full ncu profile), whereas
// a speculative tensor-core rewrite that fails correctness returns NO profile.

// Problem constants
#define BATCH 16
#define NPTS  8192
#define D     128
#define TOK   (BATCH * NPTS)   // 131072

// ---------------------------------------------------------------------------
// Scratch buffers (static __device__ — no allocations allowed)
// ---------------------------------------------------------------------------
__device__ float g_H [TOK * D];          // main activation (b,n,d)   64 MB
__device__ float g_T1[TOK * D];          // temp activation           64 MB
__device__ float g_S [BATCH * D * D];    // per-batch 128x128 (score / xh)
__device__ float g_S2[BATCH * D * D];    // per-batch 128x128 (xh2 transposed)
__device__ float g_P [8 * BATCH * D * D];// split-K partials (8 MB)
__device__ float g_CWT[D * D * D];       // transposed conv weight (8 MB)

__device__ __forceinline__ float gelu_f(float v) {
    return 0.5f * v * (1.0f + erff(v * 0.70710678118654752f));
}

// ---------------------------------------------------------------------------
// lift: T[tok, :] = gelu(x0*w1[0,:] + x1*w1[1,:] + b1)
// one thread per (token, 4-channel group)
// ---------------------------------------------------------------------------
__global__ void __launch_bounds__(256) lift_kernel(
    const float* __restrict__ x, const float* __restrict__ w1,
    const float* __restrict__ b1, float* __restrict__ T)
{
    size_t gid = (size_t)blockIdx.x * 256 + threadIdx.x;   // TOK*32 threads
    size_t tok = gid >> 5;
    int    cg  = (int)(gid & 31);
    float x0 = x[tok * 2 + 0];
    float x1 = x[tok * 2 + 1];
    float4 w0 = ((const float4*)w1)[cg];
    float4 w1r = ((const float4*)w1)[32 + cg];
    float4 bb = ((const float4*)b1)[cg];
    float4 v;
    v.x = gelu_f(x0 * w0.x + x1 * w1r.x + bb.x);
    v.y = gelu_f(x0 * w0.y + x1 * w1r.y + bb.y);
    v.z = gelu_f(x0 * w0.z + x1 * w1r.z + bb.z);
    v.w = gelu_f(x0 * w0.w + x1 * w1r.w + bb.w);
    ((float4*)T)[tok * 32 + cg] = v;
}

// ---------------------------------------------------------------------------
// Generic token GEMM:  Y = [res +] act( X @ W_b [+ bias] [+ add] )
//   X: (rows 64 per block) x 128, W: 128x128 (optionally per-batch)
//   grid = (NPTS/64, BATCH), block = 256
// Template flags: XB = X is per-batch activation; WB = W per-batch;
//   BIAS, ADD (pre-act add), GELU_, RES (post-act residual add)
// ---------------------------------------------------------------------------
template<bool XB, bool WB, bool BIAS, bool ADD, bool GELU_, bool RES>
__global__ void __launch_bounds__(256) gemm_tok(
    const float* __restrict__ X, const float* __restrict__ W,
    const float* __restrict__ bias, const float* __restrict__ add,
    const float* __restrict__ res, float* __restrict__ Y)
{
    __shared__ float sW[32 * 128];   // [k][c], 32-k chunk
    __shared__ float sX[64 * 36];    // [r][k], stride 36

    const int b    = blockIdx.y;
    const int row0 = blockIdx.x * 64;
    const float* Xp = X + (XB ? (size_t)b * NPTS * D : 0) + (size_t)row0 * D;
    const float* Wp = W + (WB ? (size_t)b * D * D : 0);
    const size_t obase = ((size_t)b * NPTS + row0) * D;
    const int t  = threadIdx.x;
    const int cg = t & 15;           // 16 col groups of 8
    const int rg = t >> 4;           // 16 row groups of 4

    float acc[4][8];
#pragma unroll
    for (int i = 0; i < 4; i++)
#pragma unroll
        for (int j = 0; j < 8; j++) acc[i][j] = 0.0f;

    const float4* Xv = (const float4*)Xp;
    const float4* Wv = (const float4*)Wp;

#pragma unroll 1
    for (int kc = 0; kc < 4; kc++) {
        // load W rows [kc*32, kc*32+32): 4096 floats = 1024 float4
#pragma unroll
        for (int i = 0; i < 4; i++) {
            int idx = t + 256 * i;
            ((float4*)sW)[idx] = Wv[kc * 1024 + idx];
        }
        // load X cols [kc*32, kc*32+32) for 64 rows: 512 float4
#pragma unroll
        for (int i = 0; i < 2; i++) {
            int idx = t + 256 * i;
            int r = idx >> 3, c = idx & 7;
            *(float4*)&sX[r * 36 + c * 4] = Xv[r * 32 + kc * 8 + c];
        }
        __syncthreads();

        const float* sXr = &sX[(rg * 4) * 36];
        const float* sWc = &sW[cg * 8];
#pragma unroll
        for (int k = 0; k < 32; k++) {
            float a0 = sXr[k];
            float a1 = sXr[36 + k];
            float a2 = sXr[72 + k];
            float a3 = sXr[108 + k];
            float4 b0 = *(const float4*)&sWc[k * 128];
            float4 b1 = *(const float4*)&sWc[k * 128 + 4];
            acc[0][0] += a0 * b0.x; acc[0][1] += a0 * b0.y; acc[0][2] += a0 * b0.z; acc[0][3] += a0 * b0.w;
            acc[0][4] += a0 * b1.x; acc[0][5] += a0 * b1.y; acc[0][6] += a0 * b1.z; acc[0][7] += a0 * b1.w;
            acc[1][0] += a1 * b0.x; acc[1][1] += a1 * b0.y; acc[1][2] += a1 * b0.z; acc[1][3] += a1 * b0.w;
            acc[1][4] += a1 * b1.x; acc[1][5] += a1 * b1.y; acc[1][6] += a1 * b1.z; acc[1][7] += a1 * b1.w;
            acc[2][0] += a2 * b0.x; acc[2][1] += a2 * b0.y; acc[2][2] += a2 * b0.z; acc[2][3] += a2 * b0.w;
            acc[2][4] += a2 * b1.x; acc[2][5] += a2 * b1.y; acc[2][6] += a2 * b1.z; acc[2][7] += a2 * b1.w;
            acc[3][0] += a3 * b0.x; acc[3][1] += a3 * b0.y; acc[3][2] += a3 * b0.z; acc[3][3] += a3 * b0.w;
            acc[3][4] += a3 * b1.x; acc[3][5] += a3 * b1.y; acc[3][6] += a3 * b1.z; acc[3][7] += a3 * b1.w;
        }
        __syncthreads();
    }

    // epilogue
    float bv[8];
    if (BIAS) {
#pragma unroll
        for (int j = 0; j < 8; j++) bv[j] = bias[cg * 8 + j];
    }
    const float* addp = ADD ? add + obase : nullptr;
    const float* resp = RES ? res + obase : nullptr;
    float* yp = Y + obase;
#pragma unroll
    for (int i = 0; i < 4; i++) {
        int ro = (rg * 4 + i) * 128 + cg * 8;
        float v[8];
#pragma unroll
        for (int j = 0; j < 8; j++) {
            float u = acc[i][j];
            if (BIAS)  u += bv[j];
            if (ADD)   u += addp[ro + j];
            if (GELU_) u = gelu_f(u);
            if (RES)   u += resp[ro + j];
            v[j] = u;
        }
        *(float4*)&yp[ro]     = make_float4(v[0], v[1], v[2], v[3]);
        *(float4*)&yp[ro + 4] = make_float4(v[4], v[5], v[6], v[7]);
    }
}

// ---------------------------------------------------------------------------
// reduce_proj: P[nc][b][d][k] = sum_{n in chunk nc} X[b,n,d] * Bm[n,k]
//   grid = (8 n-chunks, BATCH, 4 k-slices of 32), block = 256
//   Deterministic split-K: partials combined by combine8.
// ---------------------------------------------------------------------------
__global__ void __launch_bounds__(256) reduce_proj(
    const float* __restrict__ X, const float* __restrict__ Bm,
    float* __restrict__ P)
{
    const int nc = blockIdx.x, b = blockIdx.y, kc = blockIdx.z;
    const int NSPAN = NPTS / 8;   // 1024
    const int n0 = nc * NSPAN;
    const float* Xp = X + ((size_t)b * NPTS + n0) * D;
    const float* Bp = Bm + (size_t)n0 * D;
    const int t  = threadIdx.x;
    const int kg = t & 7;         // 8 groups of 4 k
    const int dg = t >> 3;        // 32 groups of 4 d

    __shared__ float sX[32 * 132];
    __shared__ float sB[32 * 36];

    float acc[4][4];
#pragma unroll
    for (int i = 0; i < 4; i++)
#pragma unroll
        for (int j = 0; j < 4; j++) acc[i][j] = 0.0f;

    const float4* Xv = (const float4*)Xp;

    for (int nt = 0; nt < NSPAN; nt += 32) {
        // X tile: 32 rows x 128 = 1024 float4
#pragma unroll
        for (int i = 0; i < 4; i++) {
            int idx = t + 256 * i;
            int r = idx >> 5, c = idx & 31;
            *(float4*)&sX[r * 132 + c * 4] = Xv[(size_t)(nt + r) * 32 + c];
        }
        // B tile: 32 rows x 32 cols (slice kc*32)
        {
            int r = t >> 3, c = t & 7;
            *(float4*)&sB[r * 36 + c * 4] =
                *(const float4*)&Bp[(size_t)(nt + r) * D + kc * 32 + c * 4];
        }
        __syncthreads();
#pragma unroll 8
        for (int n = 0; n < 32; n++) {
            float4 a = *(const float4*)&sX[n * 132 + dg * 4];
            float4 bb = *(const float4*)&sB[n * 36 + kg * 4];
            acc[0][0] += a.x * bb.x; acc[0][1] += a.x * bb.y; acc[0][2] += a.x * bb.z; acc[0][3] += a.x * bb.w;
            acc[1][0] += a.y * bb.x; acc[1][1] += a.y * bb.y; acc[1][2] += a.y * bb.z; acc[1][3] += a.y * bb.w;
            acc[2][0] += a.z * bb.x; acc[2][1] += a.z * bb.y; acc[2][2] += a.z * bb.z; acc[2][3] += a.z * bb.w;
            acc[3][0] += a.w * bb.x; acc[3][1] += a.w * bb.y; acc[3][2] += a.w * bb.z; acc[3][3] += a.w * bb.w;
        }
        __syncthreads();
    }

    float* Pp = P + (size_t)nc * (BATCH * D * D) + (size_t)b * D * D;
#pragma unroll
    for (int i = 0; i < 4; i++)
#pragma unroll
        for (int j = 0; j < 4; j++)
            Pp[(dg * 4 + i) * D + kc * 32 + kg * 4 + j] = acc[i][j];
}

__global__ void __launch_bounds__(256) combine8(
    const float* __restrict__ P, float* __restrict__ S)
{
    size_t i = (size_t)blockIdx.x * 256 + threadIdx.x;  // BATCH*D*D
    float s = 0.0f;
#pragma unroll
    for (int nc = 0; nc < 8; nc++) s += P[(size_t)nc * (BATCH * D * D) + i];
    S[i] = s;
}

// ---------------------------------------------------------------------------
// Transpose conv weight: cwt[k][i*128+o] = cw[(i*128+o)*128 + k]
//   in: (16384 x 128), out: (128 x 16384); 32x32 tiles, block (32,8)
// ---------------------------------------------------------------------------
__global__ void transp_cw(const float* __restrict__ in, float* __restrict__ out)
{
    __shared__ float tile[32][33];
    const int r0 = blockIdx.x * 32;   // io dim (16384/32 = 512)
    const int c0 = blockIdx.y * 32;   // k dim  (128/32 = 4)
    const int tx = threadIdx.x, ty = threadIdx.y;
#pragma unroll
    for (int j = 0; j < 32; j += 8)
        tile[ty + j][tx] = in[(size_t)(r0 + ty + j) * 128 + c0 + tx];
    __syncthreads();
#pragma unroll
    for (int j = 0; j < 32; j += 8)
        out[(size_t)(c0 + ty + j) * 16384 + r0 + tx] = tile[tx][ty + j];
}

// ---------------------------------------------------------------------------
// mode_apply: S2[b][k][o] = sum_i S[b][i][k] * cwt[k][i][o]
//   grid = (128 modes, BATCH), block = 128 (o)
// ---------------------------------------------------------------------------
__global__ void __launch_bounds__(128) mode_apply(
    const float* __restrict__ S, const float* __restrict__ cwt,
    float* __restrict__ S2)
{
    const int k = blockIdx.x, b = blockIdx.y, o = threadIdx.x;
    __shared__ float sxh[128];
    sxh[o] = S[(size_t)b * (D * D) + (size_t)o * D + k];
    __syncthreads();
    const float* wp = cwt + (size_t)k * (D * D) + o;
    float acc = 0.0f;
#pragma unroll 8
    for (int i = 0; i < 128; i++) acc += sxh[i] * wp[(size_t)i * D];
    S2[(size_t)b * (D * D) + (size_t)k * D + o] = acc;
}

// ---------------------------------------------------------------------------
// head: out[tok] = dot(T[tok,:], w) + b   (warp per token)
// ---------------------------------------------------------------------------
__global__ void __launch_bounds__(256) head_kernel(
    const float* __restrict__ T, const float* __restrict__ w,
    const float* __restrict__ bptr, float* __restrict__ out)
{
    const int warp = (blockIdx.x * 256 + threadIdx.x) >> 5;
    const int lane = threadIdx.x & 31;
    float4 a  = ((const float4*)T)[(size_t)warp * 32 + lane];
    float4 wv = ((const float4*)w)[lane];
    float s = a.x * wv.x + a.y * wv.y + a.z * wv.z + a.w * wv.w;
#pragma unroll
    for (int off = 16; off; off >>= 1) s += __shfl_xor_sync(0xFFFFFFFFu, s, off);
    if (lane == 0) out[warp] = s + bptr[0];
}

// ---------------------------------------------------------------------------
// Host-side launch helpers
// ---------------------------------------------------------------------------
template<bool XB, bool WB, bool BIAS, bool ADD, bool GELU_, bool RES>
static void G(const float* X, const float* W, const float* bias,
              const float* add, const float* res, float* Y)
{
    gemm_tok<XB, WB, BIAS, ADD, GELU_, RES>
        <<<dim3(NPTS / 64, BATCH), 256>>>(X, W, bias, add, res, Y);
}

extern "C" void kernel_launch(void* const* d_in, const int* in_sizes, int n_in,
                              void* d_out, int out_size)
{
    const float* x      = (const float*)d_in[0];
    const float* Bm     = (const float*)d_in[1];
    const float* fc0_w1 = (const float*)d_in[2];
    const float* fc0_b1 = (const float*)d_in[3];
    const float* fc0_w2 = (const float*)d_in[4];
    const float* fc0_b2 = (const float*)d_in[5];
    const float* a0_wk  = (const float*)d_in[6];
    const float* a0_bk  = (const float*)d_in[7];
    const float* a0_f1w = (const float*)d_in[8];
    const float* a0_f1b = (const float*)d_in[9];
    const float* a0_f2w = (const float*)d_in[10];
    const float* a0_f2b = (const float*)d_in[11];
    const float* c1_w   = (const float*)d_in[12];
    const float* w1_w   = (const float*)d_in[13];
    const float* w1_b   = (const float*)d_in[14];
    const float* a2_wk  = (const float*)d_in[15];
    const float* a2_bk  = (const float*)d_in[16];
    const float* a2_f1w = (const float*)d_in[17];
    const float* a2_f1b = (const float*)d_in[18];
    const float* a2_f2w = (const float*)d_in[19];
    const float* a2_f2b = (const float*)d_in[20];
    const float* c3_w   = (const float*)d_in[21];
    const float* w3_w   = (const float*)d_in[22];
    const float* w3_b   = (const float*)d_in[23];
    const float* fc1_w  = (const float*)d_in[24];
    const float* fc1_b  = (const float*)d_in[25];
    const float* fc2_w  = (const float*)d_in[26];
    const float* fc2_b  = (const float*)d_in[27];

    float *H, *T1, *S, *S2, *P, *CWT;
    cudaGetSymbolAddress((void**)&H,   g_H);
    cudaGetSymbolAddress((void**)&T1,  g_T1);
    cudaGetSymbolAddress((void**)&S,   g_S);
    cudaGetSymbolAddress((void**)&S2,  g_S2);
    cudaGetSymbolAddress((void**)&P,   g_P);
    cudaGetSymbolAddress((void**)&CWT, g_CWT);

    // ---- lift: h = gelu(x @ fc0_w1 + fc0_b1) @ fc0_w2 + fc0_b2 ----
    lift_kernel<<<TOK * 32 / 256, 256>>>(x, fc0_w1, fc0_b1, T1);
    G<true, false, true, false, false, false>(T1, fc0_w2, fc0_b2, nullptr, nullptr, H);

    // ---- DoubleAttention (layer 0 and layer 2) ----
    const float* wk[2]  = {a0_wk,  a2_wk};
    const float* bk[2]  = {a0_bk,  a2_bk};
    const float* f1w[2] = {a0_f1w, a2_f1w};
    const float* f1b[2] = {a0_f1b, a2_f1b};
    const float* f2w[2] = {a0_f2w, a2_f2w};
    const float* f2b[2] = {a0_f2b, a2_f2b};
    const float* cw[2]  = {c1_w, c3_w};
    const float* ww[2]  = {w1_w, w3_w};
    const float* wb[2]  = {w1_b, w3_b};

    for (int L = 0; L < 2; L++) {
        // --- attention block ---
        // key = H @ wk + bk
        G<true, false, true, false, false, false>(H, wk[L], bk[L], nullptr, nullptr, T1);
        // score = key^T @ B  (split-K partials, deterministic combine)
        reduce_proj<<<dim3(8, BATCH, 4), 256>>>(T1, Bm, P);
        combine8<<<(BATCH * D * D) / 256, 256>>>(P, S);
        // H = gelu(B @ score) + H
        G<false, true, false, false, true, true>(Bm, S, nullptr, nullptr, H, H);
        // FFN: H = H + gelu(H @ f1w + f1b) @ f2w + f2b
        G<true, false, true, false, true, false>(H, f1w[L], f1b[L], nullptr, nullptr, T1);
        G<true, false, true, false, false, true>(T1, f2w[L], f2b[L], nullptr, H, H);

        // --- GalerkinConv + Conv1d block ---
        transp_cw<<<dim3(512, 4), dim3(32, 8)>>>(cw[L], CWT);
        // xh = H^T @ B
        reduce_proj<<<dim3(8, BATCH, 4), 256>>>(H, Bm, P);
        combine8<<<(BATCH * D * D) / 256, 256>>>(P, S);
        // per-mode channel mix (writes transposed: S2[b][k][o])
        mode_apply<<<dim3(D, BATCH), 128>>>(S, CWT, S2);
        // conv1d branch: T1 = H @ ww + wb
        G<true, false, true, false, false, false>(H, ww[L], wb[L], nullptr, nullptr, T1);
        // combine: H = H + act(B @ S2 + T1);  act = gelu for layer 1, identity for layer 3
        if (L == 0)
            G<false, true, false, true, true,  true>(Bm, S2, nullptr, T1, H, H);
        else
            G<false, true, false, true, false, true>(Bm, S2, nullptr, T1, H, H);
    }

    // ---- head: out = gelu(H @ fc1_w + fc1_b) @ fc2_w + fc2_b ----
    G<true, false, true, false, true, false>(H, fc1_w, fc1_b, nullptr, nullptr, T1);
    head_kernel<<<TOK / 8, 256>>>(T1, fc2_w, fc2_b, (float*)d_out);
}

// round 10
// speedup vs baseline: 2.3061x; 2.3061x over previous
#include <cuda_runtime.h>
#include <math.h>
#include <stdint.h>

// R9: identical to R6-R8 (four broker GPUAcquisitionTimeouts; never ran).
// Broker failures are pre-container capacity — uncorrelated with kernel.
// gemm_tok + reduce_proj on tensor pipe via mma.sync tf32 m16n8k8.
// Baseline R5: 2796us fp32 FFMA. Predicted: ~1000-1300us, rel_err ~1e-5.

#define BATCH 16
#define NPTS  8192
#define D     128
#define TOK   (BATCH * NPTS)   // 131072

__device__ float g_H [TOK * D];
__device__ float g_T1[TOK * D];
__device__ float g_S [BATCH * D * D];
__device__ float g_S2[BATCH * D * D];
__device__ float g_P [8 * BATCH * D * D];
__device__ float g_CWT[D * D * D];

__device__ __forceinline__ float gelu_f(float v) {
    return 0.5f * v * (1.0f + erff(v * 0.70710678118654752f));
}

__device__ __forceinline__ uint32_t f2tf32(float f) {
    uint32_t r;
    asm("cvt.rna.tf32.f32 %0, %1;" : "=r"(r) : "f"(f));
    return r;
}

__device__ __forceinline__ void mma_tf32(float4& d,
    uint32_t a0, uint32_t a1, uint32_t a2, uint32_t a3,
    uint32_t b0, uint32_t b1)
{
    asm volatile(
        "mma.sync.aligned.m16n8k8.row.col.f32.tf32.tf32.f32 "
        "{%0,%1,%2,%3}, {%4,%5,%6,%7}, {%8,%9}, {%0,%1,%2,%3};"
        : "+f"(d.x), "+f"(d.y), "+f"(d.z), "+f"(d.w)
        : "r"(a0), "r"(a1), "r"(a2), "r"(a3), "r"(b0), "r"(b1));
}

// ---------------------------------------------------------------------------
// lift (unchanged)
// ---------------------------------------------------------------------------
__global__ void __launch_bounds__(256) lift_kernel(
    const float* __restrict__ x, const float* __restrict__ w1,
    const float* __restrict__ b1, float* __restrict__ T)
{
    size_t gid = (size_t)blockIdx.x * 256 + threadIdx.x;
    size_t tok = gid >> 5;
    int    cg  = (int)(gid & 31);
    float x0 = x[tok * 2 + 0];
    float x1 = x[tok * 2 + 1];
    float4 w0 = ((const float4*)w1)[cg];
    float4 w1r = ((const float4*)w1)[32 + cg];
    float4 bb = ((const float4*)b1)[cg];
    float4 v;
    v.x = gelu_f(x0 * w0.x + x1 * w1r.x + bb.x);
    v.y = gelu_f(x0 * w0.y + x1 * w1r.y + bb.y);
    v.z = gelu_f(x0 * w0.z + x1 * w1r.z + bb.z);
    v.w = gelu_f(x0 * w0.w + x1 * w1r.w + bb.w);
    ((float4*)T)[tok * 32 + cg] = v;
}

// ---------------------------------------------------------------------------
// Token GEMM on tensor cores:  Y = [res +] act( X @ W_b [+ bias] [+ add] )
//   Block: 256 thr (8 warps), tile 128 rows x 128 cols. grid=(NPTS/128, BATCH)
//   Warp w -> rows [w*16, w*16+16), all 128 cols. K chunked by 32.
// ---------------------------------------------------------------------------
template<bool XB, bool WB, bool BIAS, bool ADD, bool GELU_, bool RES>
__global__ void __launch_bounds__(256) gemm_tok_mma(
    const float* __restrict__ X, const float* __restrict__ W,
    const float* __restrict__ bias, const float* __restrict__ add,
    const float* __restrict__ res, float* __restrict__ Y)
{
    __shared__ uint32_t sX[128][36];   // [m][k] tf32, stride 36 (conflict-free A)
    __shared__ uint32_t sW[32][136];   // [k][n] tf32, stride 136 (conflict-free B)

    const int b    = blockIdx.y;
    const int row0 = blockIdx.x * 128;
    const float* Xp = X + (XB ? (size_t)b * NPTS * D : 0) + (size_t)row0 * D;
    const float* Wp = W + (WB ? (size_t)b * D * D : 0);
    const size_t obase = ((size_t)b * NPTS + row0) * D;

    const int t    = threadIdx.x;
    const int warp = t >> 5;
    const int lane = t & 31;
    const int qr   = lane >> 2;   // 0..7
    const int qc   = lane & 3;    // 0..3
    const int m0   = warp * 16;

    float4 acc[16];
#pragma unroll
    for (int j = 0; j < 16; j++) acc[j] = make_float4(0.f, 0.f, 0.f, 0.f);

    const float4* Xv = (const float4*)Xp;
    const float4* Wv = (const float4*)Wp;

#pragma unroll 1
    for (int kc = 0; kc < 4; kc++) {
        // X tile: 128 rows x 32 k -> 1024 float4, 4 per thread
#pragma unroll
        for (int i = 0; i < 4; i++) {
            int idx = t + 256 * i;
            int r = idx >> 3, c = idx & 7;
            float4 v = Xv[r * 32 + kc * 8 + c];
            uint4 u = make_uint4(f2tf32(v.x), f2tf32(v.y), f2tf32(v.z), f2tf32(v.w));
            *(uint4*)&sX[r][c * 4] = u;
        }
        // W tile: 32 k-rows x 128 -> 1024 float4, 4 per thread
#pragma unroll
        for (int i = 0; i < 4; i++) {
            int idx = t + 256 * i;
            int r = idx >> 5, c = idx & 31;
            float4 v = Wv[(kc * 32 + r) * 32 + c];
            uint4 u = make_uint4(f2tf32(v.x), f2tf32(v.y), f2tf32(v.z), f2tf32(v.w));
            *(uint4*)&sW[r][c * 4] = u;
        }
        __syncthreads();

#pragma unroll
        for (int k0 = 0; k0 < 32; k0 += 8) {
            uint32_t a0 = sX[m0 + qr][k0 + qc];
            uint32_t a1 = sX[m0 + qr + 8][k0 + qc];
            uint32_t a2 = sX[m0 + qr][k0 + qc + 4];
            uint32_t a3 = sX[m0 + qr + 8][k0 + qc + 4];
#pragma unroll
            for (int j = 0; j < 16; j++) {
                uint32_t b0 = sW[k0 + qc][j * 8 + qr];
                uint32_t b1 = sW[k0 + qc + 4][j * 8 + qr];
                mma_tf32(acc[j], a0, a1, a2, a3, b0, b1);
            }
        }
        __syncthreads();
    }

    // epilogue: C-frag mapping: (x,y)@(lr0,col..col+1), (z,w)@(lr1,col..col+1)
    const int lr0 = m0 + qr;
    const int lr1 = lr0 + 8;
    const float* addp = ADD ? add + obase : nullptr;
    const float* resp = RES ? res + obase : nullptr;
    float* yp = Y + obase;
#pragma unroll
    for (int j = 0; j < 16; j++) {
        int col = j * 8 + qc * 2;
        float2 bv = BIAS ? *(const float2*)&bias[col] : make_float2(0.f, 0.f);

        float u0 = acc[j].x, u1 = acc[j].y, u2 = acc[j].z, u3 = acc[j].w;
        if (BIAS) { u0 += bv.x; u1 += bv.y; u2 += bv.x; u3 += bv.y; }
        if (ADD) {
            float2 a0 = *(const float2*)&addp[(size_t)lr0 * D + col];
            float2 a1 = *(const float2*)&addp[(size_t)lr1 * D + col];
            u0 += a0.x; u1 += a0.y; u2 += a1.x; u3 += a1.y;
        }
        if (GELU_) { u0 = gelu_f(u0); u1 = gelu_f(u1); u2 = gelu_f(u2); u3 = gelu_f(u3); }
        if (RES) {
            float2 r0 = *(const float2*)&resp[(size_t)lr0 * D + col];
            float2 r1 = *(const float2*)&resp[(size_t)lr1 * D + col];
            u0 += r0.x; u1 += r0.y; u2 += r1.x; u3 += r1.y;
        }
        *(float2*)&yp[(size_t)lr0 * D + col] = make_float2(u0, u1);
        *(float2*)&yp[(size_t)lr1 * D + col] = make_float2(u2, u3);
    }
}

// ---------------------------------------------------------------------------
// reduce_proj on tensor cores: P[nc][b][d][k] = sum_n X[b,n,d]*Bm[n,k]
//   grid=(8, BATCH), block 256. Output 128x128 per block, contraction 1024.
//   A[m=d][k=n] = X[n][d] (read transposed from natural tile).
// ---------------------------------------------------------------------------
__global__ void __launch_bounds__(256) reduce_proj_mma(
    const float* __restrict__ X, const float* __restrict__ Bm,
    float* __restrict__ P)
{
    __shared__ uint32_t sXn[32][136];  // [n][d] tf32
    __shared__ uint32_t sBn[32][136];  // [n][k] tf32

    const int nc = blockIdx.x, b = blockIdx.y;
    const int n0 = nc * (NPTS / 8);
    const float* Xp = X + ((size_t)b * NPTS + n0) * D;
    const float* Bp = Bm + (size_t)n0 * D;

    const int t    = threadIdx.x;
    const int warp = t >> 5;
    const int lane = t & 31;
    const int qr   = lane >> 2;
    const int qc   = lane & 3;
    const int m0   = warp * 16;    // d-rows for this warp

    float4 acc[16];
#pragma unroll
    for (int j = 0; j < 16; j++) acc[j] = make_float4(0.f, 0.f, 0.f, 0.f);

    const float4* Xv = (const float4*)Xp;
    const float4* Bv = (const float4*)Bp;

#pragma unroll 1
    for (int nt = 0; nt < NPTS / 8; nt += 32) {
        // 32 n-rows x 128: 1024 float4 each, 4 per thread
#pragma unroll
        for (int i = 0; i < 4; i++) {
            int idx = t + 256 * i;
            int r = idx >> 5, c = idx & 31;
            float4 v = Xv[(size_t)(nt + r) * 32 + c];
            *(uint4*)&sXn[r][c * 4] =
                make_uint4(f2tf32(v.x), f2tf32(v.y), f2tf32(v.z), f2tf32(v.w));
            float4 w = Bv[(size_t)(nt + r) * 32 + c];
            *(uint4*)&sBn[r][c * 4] =
                make_uint4(f2tf32(w.x), f2tf32(w.y), f2tf32(w.z), f2tf32(w.w));
        }
        __syncthreads();

#pragma unroll
        for (int k0 = 0; k0 < 32; k0 += 8) {
            // A[d][n] = sXn[n][d]
            uint32_t a0 = sXn[k0 + qc][m0 + qr];
            uint32_t a1 = sXn[k0 + qc][m0 + qr + 8];
            uint32_t a2 = sXn[k0 + qc + 4][m0 + qr];
            uint32_t a3 = sXn[k0 + qc + 4][m0 + qr + 8];
#pragma unroll
            for (int j = 0; j < 16; j++) {
                uint32_t b0 = sBn[k0 + qc][j * 8 + qr];
                uint32_t b1 = sBn[k0 + qc + 4][j * 8 + qr];
                mma_tf32(acc[j], a0, a1, a2, a3, b0, b1);
            }
        }
        __syncthreads();
    }

    float* Pp = P + (size_t)nc * (BATCH * D * D) + (size_t)b * D * D;
    const int lr0 = m0 + qr;
    const int lr1 = lr0 + 8;
#pragma unroll
    for (int j = 0; j < 16; j++) {
        int col = j * 8 + qc * 2;
        *(float2*)&Pp[(size_t)lr0 * D + col] = make_float2(acc[j].x, acc[j].y);
        *(float2*)&Pp[(size_t)lr1 * D + col] = make_float2(acc[j].z, acc[j].w);
    }
}

__global__ void __launch_bounds__(256) combine8(
    const float* __restrict__ P, float* __restrict__ S)
{
    size_t i = (size_t)blockIdx.x * 256 + threadIdx.x;
    float s = 0.0f;
#pragma unroll
    for (int nc = 0; nc < 8; nc++) s += P[(size_t)nc * (BATCH * D * D) + i];
    S[i] = s;
}

// ---------------------------------------------------------------------------
// transp_cw, mode_apply, head (unchanged)
// ---------------------------------------------------------------------------
__global__ void transp_cw(const float* __restrict__ in, float* __restrict__ out)
{
    __shared__ float tile[32][33];
    const int r0 = blockIdx.x * 32;
    const int c0 = blockIdx.y * 32;
    const int tx = threadIdx.x, ty = threadIdx.y;
#pragma unroll
    for (int j = 0; j < 32; j += 8)
        tile[ty + j][tx] = in[(size_t)(r0 + ty + j) * 128 + c0 + tx];
    __syncthreads();
#pragma unroll
    for (int j = 0; j < 32; j += 8)
        out[(size_t)(c0 + ty + j) * 16384 + r0 + tx] = tile[tx][ty + j];
}

__global__ void __launch_bounds__(128) mode_apply(
    const float* __restrict__ S, const float* __restrict__ cwt,
    float* __restrict__ S2)
{
    const int k = blockIdx.x, b = blockIdx.y, o = threadIdx.x;
    __shared__ float sxh[128];
    sxh[o] = S[(size_t)b * (D * D) + (size_t)o * D + k];
    __syncthreads();
    const float* wp = cwt + (size_t)k * (D * D) + o;
    float acc = 0.0f;
#pragma unroll 8
    for (int i = 0; i < 128; i++) acc += sxh[i] * wp[(size_t)i * D];
    S2[(size_t)b * (D * D) + (size_t)k * D + o] = acc;
}

__global__ void __launch_bounds__(256) head_kernel(
    const float* __restrict__ T, const float* __restrict__ w,
    const float* __restrict__ bptr, float* __restrict__ out)
{
    const int warp = (blockIdx.x * 256 + threadIdx.x) >> 5;
    const int lane = threadIdx.x & 31;
    float4 a  = ((const float4*)T)[(size_t)warp * 32 + lane];
    float4 wv = ((const float4*)w)[lane];
    float s = a.x * wv.x + a.y * wv.y + a.z * wv.z + a.w * wv.w;
#pragma unroll
    for (int off = 16; off; off >>= 1) s += __shfl_xor_sync(0xFFFFFFFFu, s, off);
    if (lane == 0) out[warp] = s + bptr[0];
}

// ---------------------------------------------------------------------------
// Host-side launch helpers
// ---------------------------------------------------------------------------
template<bool XB, bool WB, bool BIAS, bool ADD, bool GELU_, bool RES>
static void G(const float* X, const float* W, const float* bias,
              const float* add, const float* res, float* Y)
{
    gemm_tok_mma<XB, WB, BIAS, ADD, GELU_, RES>
        <<<dim3(NPTS / 128, BATCH), 256>>>(X, W, bias, add, res, Y);
}

extern "C" void kernel_launch(void* const* d_in, const int* in_sizes, int n_in,
                              void* d_out, int out_size)
{
    const float* x      = (const float*)d_in[0];
    const float* Bm     = (const float*)d_in[1];
    const float* fc0_w1 = (const float*)d_in[2];
    const float* fc0_b1 = (const float*)d_in[3];
    const float* fc0_w2 = (const float*)d_in[4];
    const float* fc0_b2 = (const float*)d_in[5];
    const float* a0_wk  = (const float*)d_in[6];
    const float* a0_bk  = (const float*)d_in[7];
    const float* a0_f1w = (const float*)d_in[8];
    const float* a0_f1b = (const float*)d_in[9];
    const float* a0_f2w = (const float*)d_in[10];
    const float* a0_f2b = (const float*)d_in[11];
    const float* c1_w   = (const float*)d_in[12];
    const float* w1_w   = (const float*)d_in[13];
    const float* w1_b   = (const float*)d_in[14];
    const float* a2_wk  = (const float*)d_in[15];
    const float* a2_bk  = (const float*)d_in[16];
    const float* a2_f1w = (const float*)d_in[17];
    const float* a2_f1b = (const float*)d_in[18];
    const float* a2_f2w = (const float*)d_in[19];
    const float* a2_f2b = (const float*)d_in[20];
    const float* c3_w   = (const float*)d_in[21];
    const float* w3_w   = (const float*)d_in[22];
    const float* w3_b   = (const float*)d_in[23];
    const float* fc1_w  = (const float*)d_in[24];
    const float* fc1_b  = (const float*)d_in[25];
    const float* fc2_w  = (const float*)d_in[26];
    const float* fc2_b  = (const float*)d_in[27];

    float *H, *T1, *S, *S2, *P, *CWT;
    cudaGetSymbolAddress((void**)&H,   g_H);
    cudaGetSymbolAddress((void**)&T1,  g_T1);
    cudaGetSymbolAddress((void**)&S,   g_S);
    cudaGetSymbolAddress((void**)&S2,  g_S2);
    cudaGetSymbolAddress((void**)&P,   g_P);
    cudaGetSymbolAddress((void**)&CWT, g_CWT);

    // ---- lift ----
    lift_kernel<<<TOK * 32 / 256, 256>>>(x, fc0_w1, fc0_b1, T1);
    G<true, false, true, false, false, false>(T1, fc0_w2, fc0_b2, nullptr, nullptr, H);

    const float* wk[2]  = {a0_wk,  a2_wk};
    const float* bk[2]  = {a0_bk,  a2_bk};
    const float* f1w[2] = {a0_f1w, a2_f1w};
    const float* f1b[2] = {a0_f1b, a2_f1b};
    const float* f2w[2] = {a0_f2w, a2_f2w};
    const float* f2b[2] = {a0_f2b, a2_f2b};
    const float* cw[2]  = {c1_w, c3_w};
    const float* ww[2]  = {w1_w, w3_w};
    const float* wb[2]  = {w1_b, w3_b};

    for (int L = 0; L < 2; L++) {
        // --- attention block ---
        G<true, false, true, false, false, false>(H, wk[L], bk[L], nullptr, nullptr, T1);
        reduce_proj_mma<<<dim3(8, BATCH), 256>>>(T1, Bm, P);
        combine8<<<(BATCH * D * D) / 256, 256>>>(P, S);
        G<false, true, false, false, true, true>(Bm, S, nullptr, nullptr, H, H);
        G<true, false, true, false, true, false>(H, f1w[L], f1b[L], nullptr, nullptr, T1);
        G<true, false, true, false, false, true>(T1, f2w[L], f2b[L], nullptr, H, H);

        // --- GalerkinConv + Conv1d block ---
        transp_cw<<<dim3(512, 4), dim3(32, 8)>>>(cw[L], CWT);
        reduce_proj_mma<<<dim3(8, BATCH), 256>>>(H, Bm, P);
        combine8<<<(BATCH * D * D) / 256, 256>>>(P, S);
        mode_apply<<<dim3(D, BATCH), 128>>>(S, CWT, S2);
        G<true, false, true, false, false, false>(H, ww[L], wb[L], nullptr, nullptr, T1);
        if (L == 0)
            G<false, true, false, true, true,  true>(Bm, S2, nullptr, T1, H, H);
        else
            G<false, true, false, true, false, true>(Bm, S2, nullptr, T1, H, H);
    }

    // ---- head ----
    G<true, false, true, false, true, false>(H, fc1_w, fc1_b, nullptr, nullptr, T1);
    head_kernel<<<TOK / 8, 256>>>(T1, fc2_w, fc2_b, (float*)d_out);
}